// round 5
// baseline (speedup 1.0000x reference)
#include <cuda_runtime.h>
#include <cuda_bf16.h>
#include <cstdint>

// Embedding gather: out[t, :] = weight[token_ids[t], :]
// d_in[0] = token_ids (int32), 8192   d_in[1] = weight fp32 [32000,1024]
// d_out   = fp32 [8192,1024]
//
// 256-bit datapath variant: one CTA per token row, 128 threads, each thread
// moves 32 bytes via ld.global.nc.v8.f32 / st.global.v8.f32 (LDG.E.256 /
// STG.E.256 on sm_103a). Halves instruction + wavefront count vs float4.

static constexpr int THREADS = 128;   // 128 thr * 32 B = 4096 B row

__global__ __launch_bounds__(THREADS)
void embedding_gather_v8_kernel(const int* __restrict__ token_ids,
                                const float* __restrict__ weight,
                                float* __restrict__ out) {
    const int t = blockIdx.x;
    const int row = __ldg(token_ids + t);

    const float* src = weight + (size_t)row * 1024 + threadIdx.x * 8;
    float*       dst = out    + (size_t)t   * 1024 + threadIdx.x * 8;

    float r0, r1, r2, r3, r4, r5, r6, r7;
    asm volatile(
        "ld.global.nc.v8.f32 {%0, %1, %2, %3, %4, %5, %6, %7}, [%8];"
        : "=f"(r0), "=f"(r1), "=f"(r2), "=f"(r3),
          "=f"(r4), "=f"(r5), "=f"(r6), "=f"(r7)
        : "l"(src));
    asm volatile(
        "st.global.v8.f32 [%0], {%1, %2, %3, %4, %5, %6, %7, %8};"
        :: "l"(dst),
           "f"(r0), "f"(r1), "f"(r2), "f"(r3),
           "f"(r4), "f"(r5), "f"(r6), "f"(r7)
        : "memory");
}

extern "C" void kernel_launch(void* const* d_in, const int* in_sizes, int n_in,
                              void* d_out, int out_size) {
    const int* token_ids = (const int*)d_in[0];
    const float* weight  = (const float*)d_in[1];
    float* out           = (float*)d_out;

    int n_tokens = in_sizes[0];   // 8192

    embedding_gather_v8_kernel<<<n_tokens, THREADS>>>(token_ids, weight, out);
}

// round 7
// speedup vs baseline: 1.3039x; 1.3039x over previous
#include <cuda_runtime.h>
#include <cuda_bf16.h>
#include <cstdint>

// Embedding gather: out[t, :] = weight[token_ids[t], :]
// d_in[0] = token_ids (int32), 8192   d_in[1] = weight fp32 [32000,1024]
// d_out   = fp32 [8192,1024]
//
// R1 structure (1 CTA per token row, 256 threads x float4) + L2 policy:
//   - weight loads:  createpolicy evict_last + ld.global.nc.L2::cache_hint.v4
//   - output stores: st.global.cs.v4 (streaming, evict-first)
// Weight table (131 MB) > L2 (126 MB); without hints the 32 MB output write
// stream evicts gathered weight sectors and forces DRAM read misses.

static constexpr int THREADS = 256;   // 256 thr * 16 B = 4 KB row

__global__ __launch_bounds__(THREADS)
void embedding_gather_policy_kernel(const int* __restrict__ token_ids,
                                    const float4* __restrict__ weight,
                                    float4* __restrict__ out) {
    const int t = blockIdx.x;
    const int row = __ldg(token_ids + t);

    const float4* src = weight + (size_t)row * THREADS + threadIdx.x;
    float4*       dst = out    + (size_t)t   * THREADS + threadIdx.x;

    uint64_t pol;
    asm volatile("createpolicy.fractional.L2::evict_last.b64 %0, 1.0;" : "=l"(pol));

    float a, b, c, d;
    asm volatile(
        "ld.global.nc.L2::cache_hint.v4.f32 {%0, %1, %2, %3}, [%4], %5;"
        : "=f"(a), "=f"(b), "=f"(c), "=f"(d)
        : "l"(src), "l"(pol));
    asm volatile(
        "st.global.cs.v4.f32 [%0], {%1, %2, %3, %4};"
        :: "l"(dst), "f"(a), "f"(b), "f"(c), "f"(d)
        : "memory");
}

extern "C" void kernel_launch(void* const* d_in, const int* in_sizes, int n_in,
                              void* d_out, int out_size) {
    const int* token_ids = (const int*)d_in[0];
    const float4* weight = (const float4*)d_in[1];
    float4* out          = (float4*)d_out;

    int n_tokens = in_sizes[0];   // 8192

    embedding_gather_policy_kernel<<<n_tokens, THREADS>>>(token_ids, weight, out);
}